// round 14
// baseline (speedup 1.0000x reference)
#include <cuda_runtime.h>

#define BI   256
#define TT   1632
#define T1   816
#define T2   408
#define HIDD 64
#define CBD  512
#define NTOK 1024
#define NTOKEN (BI*T2)   /* 104448 */
#define M1     (BI*T1)   /* 208896 */

#define OUT_N   (BI*TT)                 /* 417792 */
#define IDX_OFF (OUT_N + 3)             /* 417795 */
#define QOFF    (IDX_OFF + NTOKEN*2)    /* 626691 */

// ---------------- scratch ---------------------------------------------------------
__device__ float g_H2[(size_t)NTOKEN * HIDD];
__device__ float g_Wcat[192 * 512];              // rows 0..63 = W_e3^T, 64..191 = Wd1m
__device__ float g_Chat[2 * NTOK * 64];
__device__ float g_chn [2 * NTOK];
__device__ float g_gam [2 * NTOK];
__device__ float g_cn2 [2 * NTOK];
__device__ float g_bcv [2 * NTOK];
__device__ int   g_cand0[NTOK];
__device__ int   g_n0;
__device__ int   g_slotOf[NTOK];
__device__ float g_c1full[(size_t)NTOK * NTOK];  // all stage-1 bases per slot
__device__ unsigned g_minU[NTOK];                // per-slot min upper bound (ordered uint)
__device__ int   g_c1idx [(size_t)NTOK * NTOK];
__device__ float g_c1base[(size_t)NTOK * NTOK];
__device__ int   g_n1[NTOK];
__device__ int   g_i0[NTOKEN], g_i1[NTOKEN], g_pid[NTOKEN];
__device__ unsigned g_h2maxsq;
__device__ float g_P0[NTOK * 128], g_P1[NTOK * 128];
__device__ float g_ptab[(size_t)NTOK * NTOK * 4];
__device__ float g_S[4096];                      // H2^T H2 (atomic accum)
__device__ float g_hsum[64];                     // sum h2 (atomic accum)
__device__ float g_M3[4096], g_w3b[64], g_bb;
__device__ float g_W2m [64 * 128];
__device__ float g_Wd2m[128 * 64];
__device__ float g_bd1x[128];
__device__ float g_bd2x[128];
__device__ double g_acc[8];

// ---------------- f32x2 packed helpers --------------------------------------------
__device__ __forceinline__ unsigned long long pk2(float lo, float hi) {
    unsigned long long r;
    asm("mov.b64 %0, {%1,%2};" : "=l"(r) : "f"(lo), "f"(hi));
    return r;
}
__device__ __forceinline__ float2 upk2(unsigned long long v) {
    float2 r;
    asm("mov.b64 {%0,%1}, %2;" : "=f"(r.x), "=f"(r.y) : "l"(v));
    return r;
}
__device__ __forceinline__ void fma2(unsigned long long& d,
                                     unsigned long long a, unsigned long long b) {
    asm("fma.rn.f32x2 %0, %1, %2, %0;" : "+l"(d) : "l"(a), "l"(b));
}
__device__ __forceinline__ unsigned fenc(float f) {
    unsigned u = __float_as_uint(f);
    return (u & 0x80000000u) ? ~u : (u | 0x80000000u);
}
__device__ __forceinline__ float fdec(unsigned u) {
    return __uint_as_float((u & 0x80000000u) ? (u ^ 0x80000000u) : ~u);
}

// ---------------- prep: init + repack ---------------------------------------------
__global__ void k_prep(const float* __restrict__ W_e2,
                       const float* __restrict__ W_e3,
                       const float* __restrict__ Wt_d1,
                       const float* __restrict__ Wt_d2,
                       const float* __restrict__ b_d1,
                       const float* __restrict__ b_d2) {
    int blk = blockIdx.x, tid = threadIdx.x;
    if (blk < 256) {
        int i = blk * 256 + tid;
        if (i < 64 * 128) {
            int o = i >> 7, c = i & 127, k = c >> 6, ii = c & 63;
            g_W2m[i] = W_e2[(o * 64 + ii) * 2 + k];
        }
        if (i < 64 * 512) {
            int r = i >> 9, d = i & 511;
            g_Wcat[i] = W_e3[d * 64 + r];
        }
        if (i < 128 * 512) {
            int n = i >> 9, d = i & 511;
            int k = n >> 6, o = n & 63;
            g_Wcat[64 * 512 + i] = Wt_d1[(d * 64 + o) * 2 + k];
        }
        if (i < 128 * 64) {
            int n = i >> 6, d = i & 63;
            int k = n >> 6, o = n & 63;
            g_Wd2m[i] = Wt_d2[(d * 64 + o) * 2 + k];
        }
        if (i < 128) { g_bd1x[i] = b_d1[i & 63]; g_bd2x[i] = b_d2[i & 63]; }
    } else if (blk == 256) {
        if (tid < 8) g_acc[tid] = 0.0;
        if (tid == 8) g_h2maxsq = 0u;
        #pragma unroll
        for (int q = 0; q < 4; q++) g_minU[q * 256 + tid] = 0xFFFFFFFFu;
        if (tid < 64) g_hsum[tid] = 0.f;
    } else {
        #pragma unroll
        for (int q = 0; q < 16; q++) g_S[q * 256 + tid] = 0.f;
    }
}

// =================== MEGA 1: enc | wgemm(+chnorm) | m3 | stats =====================
__global__ void __launch_bounds__(256) k_mega1(
    const float* __restrict__ img, const float* __restrict__ W_e1,
    const float* __restrict__ b_e1, const float* __restrict__ b_e2,
    const float* __restrict__ cb, const float* __restrict__ W_e3,
    const float* __restrict__ be3)
{
    __shared__ __align__(16) char sbuf[48352];
    const int tid = threadIdx.x;
    const int b = blockIdx.x;

    if (b < 408) {
        // ---------------- fused encoder ----------------
        float (*W2ts)[68] = (float(*)[68])(sbuf);                 // 34816B
        float (*As)[260]  = (float(*)[260])(sbuf + 34816);        // 8320B
        float (*imgs2)[260] = (float(*)[260])(sbuf + 43136);      // 4160B
        float* We1s = (float*)(sbuf + 47296);
        float* b1s  = (float*)(sbuf + 47808);
        float* b2s  = (float*)(sbuf + 48064);
        float* smax = (float*)(sbuf + 48320);
        const int blk = b;

        for (int e = tid; e < 8192; e += 256) {
            int o = e >> 7, c = e & 127;
            W2ts[c][o] = g_W2m[e];
        }
        if (tid < 128) We1s[tid] = W_e1[tid];
        if (tid < 64) { b1s[tid] = b_e1[tid]; b2s[tid] = b_e2[tid]; }
        {
            float4 iv = ((const float4*)img)[blk * 256 + tid];
            imgs2[0][tid] = iv.x; imgs2[1][tid] = iv.y;
            imgs2[2][tid] = iv.z; imgs2[3][tid] = iv.w;
        }
        __syncthreads();

        const int tx = tid & 7, ty = tid >> 3;
        unsigned long long acc2[8][4];
        #pragma unroll
        for (int i = 0; i < 8; i++)
            #pragma unroll
            for (int j = 0; j < 4; j++) acc2[i][j] = 0ULL;

        for (int k0 = 0; k0 < 128; k0 += 8) {
            #pragma unroll
            for (int u = 0; u < 8; u++) {
                int c = k0 + u, kp = c >> 6, ii = c & 63;
                float v = fmaf(We1s[2 * ii], imgs2[2 * kp][tid],
                         fmaf(We1s[2 * ii + 1], imgs2[2 * kp + 1][tid], b1s[ii]));
                As[u][tid] = fmaxf(v, 0.f);
            }
            __syncthreads();
            #pragma unroll
            for (int kk = 0; kk < 8; kk++) {
                int kc = k0 + kk;
                float4 a0 = *(const float4*)&As[kk][ty * 4];
                float4 a1 = *(const float4*)&As[kk][128 + ty * 4];
                float4 b0 = *(const float4*)&W2ts[kc][tx * 4];
                float4 b1v = *(const float4*)&W2ts[kc][32 + tx * 4];
                float a[8] = {a0.x, a0.y, a0.z, a0.w, a1.x, a1.y, a1.z, a1.w};
                unsigned long long bp[4] = {pk2(b0.x, b0.y), pk2(b0.z, b0.w),
                                            pk2(b1v.x, b1v.y), pk2(b1v.z, b1v.w)};
                #pragma unroll
                for (int i = 0; i < 8; i++) {
                    unsigned long long ap = pk2(a[i], a[i]);
                    #pragma unroll
                    for (int j = 0; j < 4; j++) fma2(acc2[i][j], ap, bp[j]);
                }
            }
            __syncthreads();
        }

        float mrow = 0.f;
        #pragma unroll
        for (int i = 0; i < 8; i++) {
            int rloc = (i < 4) ? (ty * 4 + i) : (128 + ty * 4 + (i - 4));
            int tok = blk * 256 + rloc;
            float ssq = 0.f;
            #pragma unroll
            for (int jj = 0; jj < 2; jj++) {
                int c0 = (jj == 0) ? (tx * 4) : (32 + tx * 4);
                float2 p0 = upk2(acc2[i][jj * 2 + 0]);
                float2 p1 = upk2(acc2[i][jj * 2 + 1]);
                float4 v;
                v.x = fmaxf(p0.x + b2s[c0 + 0], 0.f);
                v.y = fmaxf(p0.y + b2s[c0 + 1], 0.f);
                v.z = fmaxf(p1.x + b2s[c0 + 2], 0.f);
                v.w = fmaxf(p1.y + b2s[c0 + 3], 0.f);
                ssq = fmaf(v.x, v.x, ssq); ssq = fmaf(v.y, v.y, ssq);
                ssq = fmaf(v.z, v.z, ssq); ssq = fmaf(v.w, v.w, ssq);
                *(float4*)(g_H2 + (size_t)tok * 64 + c0) = v;
            }
            ssq += __shfl_xor_sync(0xffffffffu, ssq, 1);
            ssq += __shfl_xor_sync(0xffffffffu, ssq, 2);
            ssq += __shfl_xor_sync(0xffffffffu, ssq, 4);
            mrow = fmaxf(mrow, ssq);
        }
        mrow = fmaxf(mrow, __shfl_xor_sync(0xffffffffu, mrow, 8));
        mrow = fmaxf(mrow, __shfl_xor_sync(0xffffffffu, mrow, 16));
        if ((tid & 31) == 0) smax[tid >> 5] = mrow;
        __syncthreads();
        if (tid == 0) {
            float mm = smax[0];
            #pragma unroll
            for (int i = 1; i < 8; i++) mm = fmaxf(mm, smax[i]);
            atomicMax(&g_h2maxsq, __float_as_uint(mm));
        }
    } else if (b < 440) {
        // ---------------- combined weight GEMM + chnorm ----------------
        float (*As)[132] = (float(*)[132])(sbuf);          // 4224B
        float (*Bs)[132] = (float(*)[132])(sbuf + 4224);   // 4224B
        const int v = b - 408;
        const int bn = v >> 4, bm = v & 15;
        const int tx = tid & 15, ty = tid >> 4;
        const int N = 192, K = 512;

        unsigned long long acc2[8][4];
        #pragma unroll
        for (int i = 0; i < 8; i++)
            #pragma unroll
            for (int j = 0; j < 4; j++) acc2[i][j] = 0ULL;

        const int lr = tid >> 1;
        const int lc = (tid & 1) * 4;
        const float* Ap = cb + (size_t)(bm * 128 + lr) * K + lc;
        const float* Bp = g_Wcat + (size_t)(bn * 128 + lr) * K + lc;
        const bool bvalid = (bn * 128 + lr) < N;

        for (int k0 = 0; k0 < K; k0 += 8) {
            float4 av = *(const float4*)(Ap + k0);
            float4 bv = bvalid ? *(const float4*)(Bp + k0) : make_float4(0.f, 0.f, 0.f, 0.f);
            As[lc + 0][lr] = av.x; As[lc + 1][lr] = av.y; As[lc + 2][lr] = av.z; As[lc + 3][lr] = av.w;
            Bs[lc + 0][lr] = bv.x; Bs[lc + 1][lr] = bv.y; Bs[lc + 2][lr] = bv.z; Bs[lc + 3][lr] = bv.w;
            __syncthreads();
            #pragma unroll
            for (int kk = 0; kk < 8; kk++) {
                float4 a0 = *(const float4*)&As[kk][ty * 4];
                float4 a1 = *(const float4*)&As[kk][64 + ty * 4];
                float4 b0 = *(const float4*)&Bs[kk][tx * 4];
                float4 b1 = *(const float4*)&Bs[kk][64 + tx * 4];
                float a[8] = {a0.x, a0.y, a0.z, a0.w, a1.x, a1.y, a1.z, a1.w};
                unsigned long long bp[4] = {pk2(b0.x, b0.y), pk2(b0.z, b0.w),
                                            pk2(b1.x, b1.y), pk2(b1.z, b1.w)};
                #pragma unroll
                for (int i = 0; i < 8; i++) {
                    unsigned long long ap = pk2(a[i], a[i]);
                    #pragma unroll
                    for (int j = 0; j < 4; j++) fma2(acc2[i][j], ap, bp[j]);
                }
            }
            __syncthreads();
        }

        #pragma unroll
        for (int i = 0; i < 8; i++) {
            int rloc = (i < 4) ? (ty * 4 + i) : (64 + ty * 4 + i - 4);
            int r = bm * 128 + rloc;
            float ssq = 0.f;
            #pragma unroll
            for (int jj = 0; jj < 2; jj++) {
                int c0 = (jj == 0) ? (tx * 4) : (64 + tx * 4);
                int cg = bn * 128 + c0;
                if (cg < N) {
                    float2 p0 = upk2(acc2[i][jj * 2 + 0]);
                    float2 p1 = upk2(acc2[i][jj * 2 + 1]);
                    float4 vv = make_float4(p0.x, p0.y, p1.x, p1.y);
                    if (cg < 64) {
                        *(float4*)(g_Chat + (size_t)r * 64 + cg) = vv;
                        ssq = fmaf(vv.x, vv.x, ssq); ssq = fmaf(vv.y, vv.y, ssq);
                        ssq = fmaf(vv.z, vv.z, ssq); ssq = fmaf(vv.w, vv.w, ssq);
                    } else {
                        float* P = (r < NTOK) ? g_P0 : g_P1;
                        *(float4*)(P + (size_t)(r & (NTOK - 1)) * 128 + (cg - 64)) = vv;
                    }
                }
            }
            if (bn == 0) {   // chnorm: reduce ssq over tx (half-warp) and store
                ssq += __shfl_xor_sync(0xffffffffu, ssq, 1);
                ssq += __shfl_xor_sync(0xffffffffu, ssq, 2);
                ssq += __shfl_xor_sync(0xffffffffu, ssq, 4);
                ssq += __shfl_xor_sync(0xffffffffu, ssq, 8);
                if (tx == 0) g_chn[r] = sqrtf(ssq) * 1.0001f + 1e-20f;
            }
        }
    } else if (b < 457) {
        // ---------------- M3 = W^T W, w3b, bb (raw W_e3 reads) ----------------
        int v2 = b - 440;
        if (v2 < 16) {
            int idx = v2 * 256 + tid;
            int i = idx >> 6, j = idx & 63;
            float sacc = 0.f;
            for (int d = 0; d < 512; d++)
                sacc = fmaf(W_e3[d * 64 + i], W_e3[d * 64 + j], sacc);
            g_M3[idx] = sacc;
        } else {
            if (tid < 64) {
                float sacc = 0.f;
                for (int d = 0; d < 512; d++)
                    sacc = fmaf(W_e3[d * 64 + tid], be3[d], sacc);
                g_w3b[tid] = sacc;
            } else if (tid == 64) {
                float sacc = 0.f;
                for (int d = 0; d < 512; d++) { float x = be3[d]; sacc = fmaf(x, x, sacc); }
                g_bb = sacc;
            }
        }
    } else {
        // ---------------- per-code stats ----------------
        int row = (b - 457) * 8 + (tid >> 5);
        int lane = tid & 31;
        const float* r = cb + (size_t)row * CBD;
        float s = 0.f, t = 0.f;
        for (int d = lane; d < CBD; d += 32) {
            float v = r[d];
            s = fmaf(v, v, s);
            t = fmaf(v, be3[d], t);
        }
        #pragma unroll
        for (int o = 16; o; o >>= 1) {
            s += __shfl_xor_sync(0xffffffffu, s, o);
            t += __shfl_xor_sync(0xffffffffu, t, o);
        }
        if (!lane) { g_cn2[row] = s; g_bcv[row] = t; g_gam[row] = s - 2.f * t; }
    }
}

// ---------------- stage-0 candidate set -------------------------------------------
__global__ void k_cand0() {
    __shared__ float red[256];
    int tid = threadIdx.x;
    float H = sqrtf(__uint_as_float(g_h2maxsq)) * 1.0001f;
    float mn = 3.4e38f;
    for (int n = tid; n < NTOK; n += 256)
        mn = fminf(mn, g_gam[n] + 2.f * H * g_chn[n]);
    red[tid] = mn; __syncthreads();
    for (int o = 128; o; o >>= 1) {
        if (tid < o) red[tid] = fminf(red[tid], red[tid + o]);
        __syncthreads();
    }
    if (tid == 0) {
        float thresh = red[0] + 0.05f;
        int cnt = 0;
        for (int n = 0; n < NTOK; n++) {
            if (g_gam[n] - 2.f * H * g_chn[n] <= thresh) {
                g_cand0[cnt] = n; g_slotOf[n] = cnt; cnt++;
            }
        }
        g_n0 = cnt;
    }
}

// ---------------- stage-1 phase A: bases + per-slot min UB (parallel) -------------
__global__ void __launch_bounds__(256) k_s1a(const float* __restrict__ cb) {
    int s = blockIdx.y;
    if (s >= g_n0) return;
    __shared__ float c0row[512];
    __shared__ float red[128];
    const int tid = threadIdx.x;
    int v = g_cand0[s];
    if (tid < 128) ((float4*)c0row)[tid] = ((const float4*)(cb + (size_t)v * CBD))[tid];
    __syncthreads();
    float H = sqrtf(__uint_as_float(g_h2maxsq)) * 1.0001f;
    int n = blockIdx.x * 128 + (tid >> 1);
    int half = tid & 1;                         // each pair of threads splits the dot
    const float4* r1 = (const float4*)(cb + ((size_t)NTOK + n) * CBD) + half * 64;
    const float4* c0 = (const float4*)c0row + half * 64;
    float d = 0.f;
    #pragma unroll 8
    for (int k = 0; k < 64; k++) {
        float4 a = c0[k], bq = r1[k];
        d = fmaf(a.x, bq.x, d); d = fmaf(a.y, bq.y, d);
        d = fmaf(a.z, bq.z, d); d = fmaf(a.w, bq.w, d);
    }
    d += __shfl_xor_sync(0xffffffffu, d, 1);
    float mn = 3.4e38f;
    if (half == 0) {
        float base = fmaf(2.f, d, g_gam[NTOK + n]);
        g_c1full[(size_t)s * NTOK + n] = base;
        mn = base + 2.f * H * g_chn[NTOK + n];
    }
    // reduce min over even threads
    mn = fminf(mn, __shfl_xor_sync(0xffffffffu, mn, 2));
    mn = fminf(mn, __shfl_xor_sync(0xffffffffu, mn, 4));
    mn = fminf(mn, __shfl_xor_sync(0xffffffffu, mn, 8));
    mn = fminf(mn, __shfl_xor_sync(0xffffffffu, mn, 16));
    if ((tid & 31) == 0) red[tid >> 5] = mn;
    __syncthreads();
    if (tid == 0) {
        float m = red[0];
        #pragma unroll
        for (int i = 1; i < 8; i++) m = fminf(m, red[i]);
        atomicMin(&g_minU[s], fenc(m));
    }
}

// ---------------- stage-1 phase B: ordered compaction ------------------------------
__global__ void __launch_bounds__(256) k_s1b() {
    int s = blockIdx.x;
    if (s >= g_n0) return;
    __shared__ int cnt[256];
    const int tid = threadIdx.x;
    float H = sqrtf(__uint_as_float(g_h2maxsq)) * 1.0001f;
    float thresh = fdec(g_minU[s]) + 0.05f;
    float base[4]; int flag[4];
    int mycnt = 0;
    #pragma unroll
    for (int q = 0; q < 4; q++) {
        int n = tid * 4 + q;
        base[q] = g_c1full[(size_t)s * NTOK + n];
        flag[q] = (base[q] - 2.f * H * g_chn[NTOK + n] <= thresh) ? 1 : 0;
        mycnt += flag[q];
    }
    cnt[tid] = mycnt; __syncthreads();
    for (int off = 1; off < 256; off <<= 1) {
        int vv = (tid >= off) ? cnt[tid - off] : 0;
        __syncthreads();
        cnt[tid] += vv;
        __syncthreads();
    }
    int pos = cnt[tid] - mycnt;
    #pragma unroll
    for (int q = 0; q < 4; q++) {
        if (flag[q]) {
            g_c1idx [(size_t)s * NTOK + pos] = tid * 4 + q;
            g_c1base[(size_t)s * NTOK + pos] = base[q];
            pos++;
        }
    }
    if (tid == 255) g_n1[s] = cnt[255];
}

// =================== MEGA 3: vq | ptab ============================================
__global__ void __launch_bounds__(256) k_mega3(const float* __restrict__ W3,
                                               const float* __restrict__ b3,
                                               float* __restrict__ dout) {
    __shared__ __align__(16) char sbuf[35584];
    const int tid = threadIdx.x;
    const int b = blockIdx.x;

    if (b < 1632) {
        // ---------------- per-token argmin + loss terms ----------------
        double (*sm)[5] = (double(*)[5])(sbuf);
        int w = tid >> 5, lane = tid & 31;
        int n0 = g_n0;
        double a_q0x = 0, a_q1x = 0, a_c0 = 0, a_c1 = 0, a_G = 0;
        int wbase = (b * 8 + w) * 8;
        float* didx = dout + IDX_OFF;
        for (int r = 0; r < 8; r++) {
            int t = wbase + r;
            float2 h = ((const float2*)(g_H2 + (size_t)t * 64))[lane];
            float bs = 3.4e38f, bd0 = 0.f; int bi = 0;
            for (int j = 0; j < n0; j++) {
                int c = g_cand0[j];
                float2 cv = ((const float2*)(g_Chat + (size_t)c * 64))[lane];
                float p = fmaf(h.x, cv.x, h.y * cv.y);
                #pragma unroll
                for (int o = 16; o; o >>= 1) p += __shfl_xor_sync(0xffffffffu, p, o);
                float s = fmaf(-2.f, p, g_gam[c]);
                if (s < bs) { bs = s; bi = c; bd0 = p; }
            }
            int i0 = bi;
            int slot = g_slotOf[i0];
            int n1 = g_n1[slot];
            const int*   c1i = g_c1idx  + (size_t)slot * NTOK;
            const float* c1b = g_c1base + (size_t)slot * NTOK;
            bs = 3.4e38f; bi = 0; float bd1 = 0.f, bb1 = 0.f; int bj = 0;
            for (int j = 0; j < n1; j++) {
                int c = c1i[j]; float base = c1b[j];
                float2 cv = ((const float2*)(g_Chat + (size_t)(NTOK + c) * 64))[lane];
                float p = fmaf(h.x, cv.x, h.y * cv.y);
                #pragma unroll
                for (int o = 16; o; o >>= 1) p += __shfl_xor_sync(0xffffffffu, p, o);
                float s = fmaf(-2.f, p, base);
                if (s < bs) { bs = s; bi = c; bd1 = p; bb1 = base; bj = j; }
            }
            int i1 = bi;
            if (lane == 0) {
                g_i0[t] = i0; g_i1[t] = i1;
                g_pid[t] = slot * NTOK + bj;
                didx[2 * t] = (float)i0; didx[2 * t + 1] = (float)i1;
                a_q0x += (double)bd0 + (double)g_bcv[i0];
                a_q1x += (double)bd1 + (double)g_bcv[NTOK + i1];
                a_c0  += (double)g_cn2[i0];
                a_c1  += (double)g_cn2[NTOK + i1];
                a_G   += 0.5 * ((double)bb1 - (double)g_gam[NTOK + i1]);
            }
        }
        if (lane == 0) {
            sm[w][0] = a_q0x; sm[w][1] = a_q1x; sm[w][2] = a_c0; sm[w][3] = a_c1; sm[w][4] = a_G;
        }
        __syncthreads();
        if (tid == 0) {
            double v0 = 0, v1 = 0, v2 = 0, v3 = 0, v4 = 0;
            #pragma unroll
            for (int i = 0; i < 8; i++) {
                v0 += sm[i][0]; v1 += sm[i][1]; v2 += sm[i][2]; v3 += sm[i][3]; v4 += sm[i][4];
            }
            atomicAdd(&g_acc[0], v0); atomicAdd(&g_acc[1], v1);
            atomicAdd(&g_acc[3], v2); atomicAdd(&g_acc[4], v3);
            atomicAdd(&g_acc[5], v4);
        }
    } else {
        // ---------------- pair table ----------------
        int vv = b - 1632;
        int s = vv >> 4, jstart = vv & 15;
        if (s >= g_n0) return;
        float (*Wts)[128] = (float(*)[128])(sbuf);              // 32768B
        float (*d1s)[64]  = (float(*)[64])(sbuf + 32768);       // 512B
        float* bd1s = (float*)(sbuf + 33280);
        float* bd2s = (float*)(sbuf + 33792);
        float* w3s  = (float*)(sbuf + 34304);
        float* sred = (float*)(sbuf + 34560);
        for (int e = tid; e < 8192; e += 256) {
            int n = e >> 6, c = e & 63;
            Wts[c][n] = g_Wd2m[e];
        }
        if (tid < 128) { bd1s[tid] = g_bd1x[tid]; bd2s[tid] = g_bd2x[tid]; }
        if (tid < 64) w3s[tid] = W3[tid];
        const float b3v = b3[0];
        const int n1 = g_n1[s];
        const int i0 = g_cand0[s];
        const float* P0r = g_P0 + (size_t)i0 * 128;
        __syncthreads();

        const int p = tid >> 7, n = tid & 127;
        for (int j = jstart; j < n1; j += 16) {
            int i1 = g_c1idx[(size_t)s * NTOK + j];
            if (tid < 128)
                d1s[tid >> 6][tid & 63] =
                    fmaxf(P0r[tid] + g_P1[(size_t)i1 * 128 + tid] + bd1s[tid], 0.f);
            __syncthreads();
            float v = bd2s[n];
            #pragma unroll 16
            for (int c = 0; c < 64; c++) v = fmaf(d1s[p][c], Wts[c][n], v);
            v = fmaxf(v, 0.f) * w3s[n & 63];
            sred[tid] = v;
            __syncthreads();
            if ((tid & 63) < 32) {
                float x = sred[tid] + sred[tid + 32];
                #pragma unroll
                for (int o = 16; o; o >>= 1) x += __shfl_down_sync(0xffffffffu, x, o);
                if ((tid & 63) == 0)
                    g_ptab[((size_t)s * NTOK + j) * 4 + (tid >> 6)] = x + b3v;
            }
            __syncthreads();
        }
    }
}

// =================== MEGA 2: qout | out | Spart ===================================
__global__ void __launch_bounds__(256) k_mega2(const float* __restrict__ cb,
                                               const float* __restrict__ img,
                                               float* __restrict__ dout) {
    __shared__ __align__(16) char sbuf[27744];
    const int tid = threadIdx.x;
    const int b = blockIdx.x;

    if (b < 8192) {
        // ---------------- quantized output, tiled transpose ----------------
        float* sq = (float*)sbuf;                 // 408*17 floats
        const int d0 = (b & 31) * 16;
        const int bb = b >> 5;
        for (int tt = tid; tt < T2; tt += 256) {
            int tok = bb * T2 + tt;
            const float4* r0 = (const float4*)(cb + (size_t)g_i0[tok] * CBD + d0);
            const float4* r1 = (const float4*)(cb + ((size_t)NTOK + g_i1[tok]) * CBD + d0);
            #pragma unroll
            for (int q = 0; q < 4; q++) {
                float4 a = r0[q], c = r1[q];
                sq[tt * 17 + q * 4 + 0] = a.x + c.x;
                sq[tt * 17 + q * 4 + 1] = a.y + c.y;
                sq[tt * 17 + q * 4 + 2] = a.z + c.z;
                sq[tt * 17 + q * 4 + 3] = a.w + c.w;
            }
        }
        __syncthreads();
        const int w = tid >> 5, lane = tid & 31;
        #pragma unroll
        for (int it = 0; it < 2; it++) {
            int d = it * 8 + w;
            size_t base = QOFF + ((size_t)bb * CBD + d0 + d) * T2;
            #pragma unroll
            for (int j = 0; j < 13; j++) {
                int t = j * 32 + lane;
                if (t < T2) dout[base + t] = sq[t * 17 + d];
            }
        }
    } else if (b < 8600) {
        // ---------------- decoder output gather + recon loss ----------------
        double* sd = (double*)sbuf;
        int tok = (b - 8192) * 256 + tid;
        int pid = g_pid[tok];
        float4 v = ((const float4*)g_ptab)[pid];
        int bb = tok / T2, t2 = tok - bb * T2;
        size_t o = (size_t)bb * TT + 4 * t2;
        *(float4*)(dout + o) = v;
        float4 iv = *(const float4*)(img + o);
        float e0 = iv.x - v.x, e1 = iv.y - v.y, e2 = iv.z - v.z, e3 = iv.w - v.w;
        sd[tid] = (double)e0 * e0 + (double)e1 * e1 + (double)e2 * e2 + (double)e3 * e3;
        __syncthreads();
        for (int o2 = 128; o2; o2 >>= 1) {
            if (tid < o2) sd[tid] += sd[tid + o2];
            __syncthreads();
        }
        if (!tid) atomicAdd(&g_acc[2], sd[0]);
    } else {
        // ---------------- partial S = H2^T H2 (atomic accumulate) ----------------
        float* sh2 = (float*)sbuf;                // 8*64 floats
        int blk = b - 8600;
        int t0 = blk * 816;
        float acc[16];
        #pragma unroll
        for (int i = 0; i < 16; i++) acc[i] = 0.f;
        float hs = 0.f;
        int ti = tid >> 4, tj = tid & 15;
        for (int g = 0; g < 102; g++) {
            int base = t0 + g * 8;
            if (tid < 128)
                ((float4*)sh2)[tid] = ((const float4*)(g_H2 + (size_t)base * 64))[tid];
            __syncthreads();
            #pragma unroll
            for (int r = 0; r < 8; r++) {
                float4 a = *(const float4*)&sh2[r * 64 + ti * 4];
                float4 bq = *(const float4*)&sh2[r * 64 + tj * 4];
                float av[4] = {a.x, a.y, a.z, a.w}, bv[4] = {bq.x, bq.y, bq.z, bq.w};
                #pragma unroll
                for (int p = 0; p < 4; p++)
                    #pragma unroll
                    for (int q = 0; q < 4; q++) acc[p * 4 + q] = fmaf(av[p], bv[q], acc[p * 4 + q]);
            }
            if (tid < 64) {
                #pragma unroll
                for (int r = 0; r < 8; r++) hs += sh2[r * 64 + tid];
            }
            __syncthreads();
        }
        #pragma unroll
        for (int p = 0; p < 4; p++)
            #pragma unroll
            for (int q = 0; q < 4; q++)
                atomicAdd(&g_S[(ti * 4 + p) * 64 + (tj * 4 + q)], acc[p * 4 + q]);
        if (tid < 64) atomicAdd(&g_hsum[tid], hs);
    }
}

// ---------------- fin: Sfinal + scalars -------------------------------------------
__global__ void k_fin(float* __restrict__ dout) {
    __shared__ double red[256];
    int tid = threadIdx.x;
    double partial = 0.0;
    for (int c = tid; c < 4096; c += 256)
        partial += (double)g_S[c] * (double)g_M3[c];
    if (tid < 64) partial += 2.0 * (double)g_hsum[tid] * (double)g_w3b[tid];
    if (tid == 64) partial += (double)NTOKEN * (double)g_bb;
    red[tid] = partial; __syncthreads();
    for (int o = 128; o; o >>= 1) {
        if (tid < o) red[tid] += red[tid + o];
        __syncthreads();
    }
    if (tid == 0) {
        double xsq = red[0];
        double denom = (double)NTOKEN * CBD;
        double q0x = g_acc[0], q1x = g_acc[1], c0 = g_acc[3], c1 = g_acc[4];
        double G = g_acc[5];
        dout[OUT_N + 0] = (float)(g_acc[2] / (double)OUT_N);
        dout[OUT_N + 1] = (float)((c0 - 2.0 * q0x + xsq) / denom);
        dout[OUT_N + 2] = (float)((c0 + c1 + xsq + 2.0 * G - 2.0 * q0x - 2.0 * q1x) / denom);
    }
}

// ---------------- launch -----------------------------------------------------------
extern "C" void kernel_launch(void* const* d_in, const int* in_sizes, int n_in,
                              void* d_out, int out_size) {
    const float* img   = (const float*)d_in[0];
    const float* W_e1  = (const float*)d_in[1];
    const float* b_e1  = (const float*)d_in[2];
    const float* W_e2  = (const float*)d_in[3];
    const float* b_e2  = (const float*)d_in[4];
    const float* W_e3  = (const float*)d_in[5];
    const float* b_e3  = (const float*)d_in[6];
    const float* cb    = (const float*)d_in[7];
    const float* Wt_d1 = (const float*)d_in[8];
    const float* b_d1  = (const float*)d_in[9];
    const float* Wt_d2 = (const float*)d_in[10];
    const float* b_d2  = (const float*)d_in[11];
    const float* W_d3  = (const float*)d_in[12];
    const float* b_d3  = (const float*)d_in[13];
    float* out = (float*)d_out;

    k_prep <<<258, 256>>>(W_e2, W_e3, Wt_d1, Wt_d2, b_d1, b_d2);
    k_mega1<<<713, 256>>>(img, W_e1, b_e1, b_e2, cb, W_e3, b_e3);
    k_cand0<<<1, 256>>>();
    k_s1a  <<<dim3(8, NTOK), 256>>>(cb);
    k_s1b  <<<NTOK, 256>>>();
    k_mega3<<<1632 + 1024, 256>>>(W_d3, b_d3, out);
    k_mega2<<<8192 + 408 + 128, 256>>>(cb, img, out);
    k_fin  <<<1, 256>>>(out);
}